// round 13
// baseline (speedup 1.0000x reference)
#include <cuda_runtime.h>
#include <cstdint>

#define T_STEPS   1024
#define BATCH     8
#define DIM       1024
#define MROWS     8192
#define REC_CTAS  128
#define CON_CTAS  24
#define PRO_MB    2
#define REC_SMEM  ((16*1024 + 8*1024 + 256)*4)

__device__ __align__(16) float g_AD[(size_t)MROWS * 2048];
__device__ __align__(16) float g_hbuf[2 * BATCH * DIM];
__device__ float    g_scale[2];
__device__ __align__(16) double g_sud[2 * DIM];
__device__ __align__(16) double g_spartd[2 * 32 * DIM];
__device__ unsigned g_arrive;
__device__ unsigned g_release;
__device__ __align__(128) unsigned g_flags[128 * 8];
__device__ unsigned g_rel2;
__device__ int      g_mbcnt[64];

__device__ __forceinline__ void grid_barrier(unsigned relbase, unsigned nbar) {
    __syncthreads();
    if (threadIdx.x == 0) {
        __threadfence();
        unsigned a = atomicAdd(&g_arrive, 1u);
        if (a == gridDim.x - 1u) {
            atomicExch(&g_arrive, 0u);
            __threadfence();
            atomicAdd(&g_release, 1u);
        } else {
            volatile unsigned* rel = &g_release;
            while ((unsigned)(*rel - relbase) < nbar) { __nanosleep(40); }
        }
        __threadfence();
    }
    __syncthreads();
}

__device__ __forceinline__ double block_reduce_sum_d(double v, double* red) {
    __syncthreads();
    int lane = threadIdx.x & 31, w = threadIdx.x >> 5;
    #pragma unroll
    for (int o = 16; o; o >>= 1) v += __shfl_xor_sync(0xffffffffu, v, o);
    if (lane == 0) red[w] = v;
    __syncthreads();
    if (threadIdx.x == 0) {
        double t = 0.0;
        #pragma unroll
        for (int i = 0; i < 8; i++) t += red[i];
        red[0] = t;
    }
    __syncthreads();
    return red[0];
}

// ============ spectral norm in DOUBLE (unchanged) ============
__global__ void spectral_kernel(const float* __restrict__ Rh, const float* __restrict__ Rd,
                                const float* __restrict__ uh, const float* __restrict__ ud) {
    const int m = blockIdx.x >> 5;
    const int r = blockIdx.x & 31;
    const float* W  = m ? Rd : Rh;
    const float* u0 = m ? ud : uh;
    double* gu    = g_sud    + m * DIM;
    double* gpart = g_spartd + (size_t)m * 32 * DIM;
    const int tid = threadIdx.x;

    __shared__ double red[16];
    __shared__ double v_s[DIM];
    __shared__ unsigned sh_rb;
    if (tid == 0) sh_rb = *(volatile unsigned*)&g_release;
    __syncthreads();
    const unsigned relbase = sh_rb;
    unsigned nbar = 0;

    double ss = 0.0;
    for (int i = tid; i < DIM; i += 256) { double v = (double)u0[i]; ss += v * v; }
    ss = block_reduce_sum_d(ss, red);
    double inv_u = 1.0 / (sqrt(ss) + 1e-8);

    int use_u0 = 1;
    double S_last = 0.0;

    for (int it = 0; it < 3; it++) {
        double a0 = 0, a1 = 0, a2 = 0, a3 = 0;
        for (int kk = 0; kk < 32; kk++) {
            int k = r * 32 + kk;
            double uk = (use_u0 ? (double)u0[k] : gu[k]) * inv_u;
            float4 wv = *(const float4*)(W + (size_t)k * DIM + tid * 4);
            a0 += (double)wv.x * uk; a1 += (double)wv.y * uk;
            a2 += (double)wv.z * uk; a3 += (double)wv.w * uk;
        }
        double* pdst = gpart + (size_t)r * DIM + tid * 4;
        pdst[0] = a0; pdst[1] = a1; pdst[2] = a2; pdst[3] = a3;
        grid_barrier(relbase, ++nbar);

        double s0 = 0, s1 = 0, s2 = 0, s3 = 0;
        for (int rr = 0; rr < 32; rr++) {
            const double* p = gpart + (size_t)rr * DIM + tid * 4;
            s0 += p[0]; s1 += p[1]; s2 += p[2]; s3 += p[3];
        }
        v_s[tid * 4 + 0] = s0; v_s[tid * 4 + 1] = s1;
        v_s[tid * 4 + 2] = s2; v_s[tid * 4 + 3] = s3;
        double ssv = s0 * s0 + s1 * s1 + s2 * s2 + s3 * s3;
        ssv = block_reduce_sum_d(ssv, red);
        double inv_v = 1.0 / (sqrt(ssv) + 1e-8);

        {
            int wnum = tid >> 5, lane = tid & 31;
            for (int rr = 0; rr < 4; rr++) {
                int row = r * 32 + wnum * 4 + rr;
                double p = 0.0;
                for (int k = lane; k < DIM; k += 32)
                    p += (double)W[(size_t)row * DIM + k] * v_s[k];
                #pragma unroll
                for (int o = 16; o; o >>= 1) p += __shfl_down_sync(0xffffffffu, p, o);
                if (lane == 0) gu[row] = p * inv_v;
            }
        }
        grid_barrier(relbase, ++nbar);

        double s2sum = 0.0;
        for (int i = tid; i < DIM; i += 256) { double v = gu[i]; s2sum += v * v; }
        s2sum = block_reduce_sum_d(s2sum, red);
        inv_u = 1.0 / (sqrt(s2sum) + 1e-8);
        S_last = s2sum;
        use_u0 = 0;
    }

    double sigma = S_last / sqrt(S_last);
    if (r == 0 && tid == 0) g_scale[m] = (float)(0.99 / (sigma + 1e-8));
}

// ============ double-buffered 128x128 AD tile (bit-exact chains; streaming loads) ============
__device__ __forceinline__ void ad_tile(
    const float* __restrict__ x, const float* __restrict__ Rx,
    const float* __restrict__ Wdel, int m0, int n0, int tid) {

    extern __shared__ float smem[];
    float* As = smem;
    float* Bs = smem + 2048;

    const float* B; int nb;
    if (n0 < DIM) { B = Rx; nb = n0; }
    else          { B = Wdel; nb = n0 - DIM; }

    const int lr = tid >> 1;
    const int lk = (tid & 1) * 4;
    const int tx = tid & 15, ty = tid >> 4;

    float acc[8][8];
    #pragma unroll
    for (int i = 0; i < 8; i++)
        #pragma unroll
        for (int j = 0; j < 8; j++) acc[i][j] = 0.f;

    const float* Aptr = x + (size_t)(m0 + lr) * DIM + lk;
    const float* Bptr = B + (size_t)(nb + lr) * DIM + lk;

    float4 av = __ldcs((const float4*)Aptr);
    float4 bv = __ldcs((const float4*)Bptr);
    As[(lk + 0) * 128 + lr] = av.x; As[(lk + 1) * 128 + lr] = av.y;
    As[(lk + 2) * 128 + lr] = av.z; As[(lk + 3) * 128 + lr] = av.w;
    Bs[(lk + 0) * 128 + lr] = bv.x; Bs[(lk + 1) * 128 + lr] = bv.y;
    Bs[(lk + 2) * 128 + lr] = bv.z; Bs[(lk + 3) * 128 + lr] = bv.w;
    __syncthreads();

    int cur = 0;
    for (int k0 = 0; k0 < DIM; k0 += 8) {
        const bool more = (k0 + 8 < DIM);
        if (more) {
            av = __ldcs((const float4*)(Aptr + k0 + 8));
            bv = __ldcs((const float4*)(Bptr + k0 + 8));
        }
        float* Ac = As + cur * 1024;
        float* Bc = Bs + cur * 1024;
        #pragma unroll
        for (int kk = 0; kk < 8; kk++) {
            float a[8], bb[8];
            *(float4*)(a)      = *(const float4*)&Ac[kk * 128 + ty * 4];
            *(float4*)(a + 4)  = *(const float4*)&Ac[kk * 128 + 64 + ty * 4];
            *(float4*)(bb)     = *(const float4*)&Bc[kk * 128 + tx * 4];
            *(float4*)(bb + 4) = *(const float4*)&Bc[kk * 128 + 64 + tx * 4];
            #pragma unroll
            for (int i = 0; i < 8; i++)
                #pragma unroll
                for (int j = 0; j < 8; j++)
                    acc[i][j] += a[i] * bb[j];
        }
        if (more) {
            int nxt = 1 - cur;
            float* An = As + nxt * 1024;
            float* Bn = Bs + nxt * 1024;
            An[(lk + 0) * 128 + lr] = av.x; An[(lk + 1) * 128 + lr] = av.y;
            An[(lk + 2) * 128 + lr] = av.z; An[(lk + 3) * 128 + lr] = av.w;
            Bn[(lk + 0) * 128 + lr] = bv.x; Bn[(lk + 1) * 128 + lr] = bv.y;
            Bn[(lk + 2) * 128 + lr] = bv.z; Bn[(lk + 3) * 128 + lr] = bv.w;
            __syncthreads();
            cur = nxt;
        }
    }

    #pragma unroll
    for (int i = 0; i < 8; i++) {
        int m = m0 + ((i < 4) ? (ty * 4 + i) : (64 + ty * 4 + (i - 4)));
        float4 c0 = make_float4(acc[i][0], acc[i][1], acc[i][2], acc[i][3]);
        float4 c1 = make_float4(acc[i][4], acc[i][5], acc[i][6], acc[i][7]);
        *(float4*)(g_AD + (size_t)m * 2048 + n0 + tx * 4)      = c0;
        *(float4*)(g_AD + (size_t)m * 2048 + n0 + 64 + tx * 4) = c1;
    }
}

__global__ void __launch_bounds__(256) sgemm_kernel(
    const float* __restrict__ x, const float* __restrict__ Rx,
    const float* __restrict__ Wdel) {
    ad_tile(x, Rx, Wdel, blockIdx.y * 128, blockIdx.x * 128, threadIdx.x);
}

__global__ void init_kernel(const float* __restrict__ logh0, const float* __restrict__ signh0,
                            float* __restrict__ o_logh, float* __restrict__ o_sign) {
    int i = blockIdx.x * 256 + threadIdx.x;
    float lh = logh0[i], s = signh0[i];
    o_logh[i] = lh;
    o_sign[i] = s;
    g_hbuf[i] = s * expf(lh);
    if (i < 128 * 8) g_flags[i] = 0u;
    if (i < 64) g_mbcnt[i] = 0;
    if (i == 0) { g_rel2 = 0u; g_arrive = 0u; g_release = 0u; }
}

// ============ combined persistent kernel ============
__global__ void __launch_bounds__(256) recurrence_kernel(
    const float* __restrict__ Rh, const float* __restrict__ Rd,
    const float* __restrict__ x,  const float* __restrict__ Rx,
    const float* __restrict__ Wdel, const float* __restrict__ Wout,
    const float* __restrict__ bvec, const float* __restrict__ bdel,
    float* __restrict__ o_hlin, float* __restrict__ o_logh, float* __restrict__ o_sign,
    float* __restrict__ out) {

    extern __shared__ float smem[];
    const int tid = threadIdx.x;
    const int bid = blockIdx.x;

    if (bid < REC_CTAS) {
        float* W_s  = smem;
        float* h_s  = smem + 16 * 1024;
        float* part = smem + 16 * 1024 + 8 * 1024;
        const int j0  = bid * 8;

        __shared__ float bj_s[8], bdj_s[8];
        __shared__ double ds[64];
        __shared__ int   flag_n;
        __shared__ int   flag_pos[16];
        __shared__ double dred[32];
        if (tid < 8)       bj_s[tid]  = bvec[j0 + tid];
        else if (tid < 16) bdj_s[tid - 8] = bdel[j0 + tid - 8];

        const float s_h = g_scale[0];
        const float s_d = g_scale[1];

        for (int idx = tid; idx < 2048; idx += 256) {
            int row = idx >> 8;
            int c4  = idx & 255;
            float4 a = *(const float4*)(Rh + (size_t)(j0 + row) * DIM + c4 * 4);
            a.x *= s_h; a.y *= s_h; a.z *= s_h; a.w *= s_h;
            ((float4*)(W_s + (size_t)row * DIM))[c4] = a;
            float4 d = *(const float4*)(Rd + (size_t)(j0 + row) * DIM + c4 * 4);
            d.x *= s_d; d.y *= s_d; d.z *= s_d; d.w *= s_d;
            ((float4*)(W_s + (size_t)(8 + row) * DIM))[c4] = d;
        }
        __syncthreads();

        const int w  = tid >> 5, l = tid & 31;
        const int kh = w >> 2;
        const int cg = (w & 3) << 2;
        const int ei  = tid & 63;
        const int elc = ei >> 3, eb = ei & 7;

        for (int t = 0; t < T_STEPS; t++) {
            if ((t & 15) == 0 && t >= PRO_MB * 16) {
                volatile int* c = &g_mbcnt[t >> 4];
                while (*c < 16) { }
            }

            float ad_pf = 0.f;
            {
                size_t prow = (size_t)t * BATCH + eb;
                if (tid < 64)       ad_pf = __ldcg(&g_AD[prow * 2048 + j0 + elc]);
                else if (tid < 128) ad_pf = __ldcg(&g_AD[prow * 2048 + 1024 + j0 + elc]);
            }
            if (tid == 0) flag_n = 0;

            const float* hsrc = g_hbuf + (size_t)(t & 1) * (BATCH * DIM);
            for (int i = tid; i < 2048; i += 256)
                ((float4*)h_s)[i] = __ldcg(((const float4*)hsrc) + i);
            __syncthreads();

            float acc[4][8];
            #pragma unroll
            for (int c = 0; c < 4; c++)
                #pragma unroll
                for (int b = 0; b < 8; b++) acc[c][b] = 0.f;

            #pragma unroll
            for (int i = 0; i < 4; i++) {
                int kb = (kh << 9) + (i << 7) + (l << 2);
                float4 w4[4];
                #pragma unroll
                for (int c = 0; c < 4; c++)
                    w4[c] = *(const float4*)(W_s + (size_t)(cg + c) * DIM + kb);
                #pragma unroll
                for (int b = 0; b < 8; b++) {
                    float4 h4 = *(const float4*)(h_s + (size_t)b * DIM + kb);
                    #pragma unroll
                    for (int c = 0; c < 4; c++)
                        acc[c][b] += w4[c].x * h4.x + w4[c].y * h4.y
                                   + w4[c].z * h4.z + w4[c].w * h4.w;
                }
            }
            #pragma unroll
            for (int o = 16; o; o >>= 1)
                #pragma unroll
                for (int c = 0; c < 4; c++)
                    #pragma unroll
                    for (int b = 0; b < 8; b++)
                        acc[c][b] += __shfl_down_sync(0xffffffffu, acc[c][b], o);
            if (l == 0) {
                #pragma unroll
                for (int c = 0; c < 4; c++)
                    #pragma unroll
                    for (int b = 0; b < 8; b++)
                        part[(cg + c) * 16 + b * 2 + kh] = acc[c][b];
            }
            __syncthreads();

            double cand_r = 0.0;
            if (tid < 64) {
                double hv = (double)part[elc * 16 + eb * 2 + 0] + (double)part[elc * 16 + eb * 2 + 1];
                cand_r = tanh((double)ad_pf + hv + (double)bj_s[elc]);
            } else if (tid < 128) {
                double dv = (double)part[(8 + elc) * 16 + eb * 2 + 0] + (double)part[(8 + elc) * 16 + eb * 2 + 1];
                ds[ei] = 1.0 / (1.0 + exp(-((double)ad_pf + dv + (double)bdj_s[elc])));
            }
            if (tid < 128)
                asm volatile("bar.sync 1, 128;" ::: "memory");

            if (tid < 64) {
                int j = j0 + elc;
                size_t row = (size_t)t * BATCH + eb;
                double delta = ds[ei];
                double hp = (double)h_s[(size_t)eb * DIM + j];
                double hnd = (1.0 - delta) * hp + delta * cand_r;
                float hn = (float)hnd;
                float lh = (float)log((double)fabsf(hn) + 1e-12);
                float sg = (hn >= 0.f) ? 1.f : -1.f;
                __stcg(&g_hbuf[(size_t)((t + 1) & 1) * (BATCH * DIM) + (size_t)eb * DIM + j],
                       sg * (float)exp((double)lh));
                o_hlin[row * DIM + j] = hn;
                o_logh[(row + BATCH) * DIM + j] = lh;
                o_sign[(row + BATCH) * DIM + j] = sg;
                if (fabsf(hn) < 4e-6f) {
                    int fi = atomicAdd(&flag_n, 1);
                    if (fi < 16) flag_pos[fi] = (eb << 16) | elc;
                }
            }
            __syncthreads();

            int nf = flag_n; if (nf > 16) nf = 16;
            for (int f = 0; f < nf; f++) {
                int pb  = flag_pos[f] >> 16;
                int plc = flag_pos[f] & 0xffff;
                int pj  = j0 + plc;
                size_t prow = (size_t)t * BATCH + pb;
                const float* xr = x + prow * DIM;
                const float* hb = h_s + (size_t)pb * DIM;
                double sa = 0, sd2 = 0, sh2 = 0, sv2 = 0;
                for (int k = tid; k < DIM; k += 256) {
                    double xk = (double)xr[k], hk = (double)hb[k];
                    sa  += xk * (double)Rx  [(size_t)pj * DIM + k];
                    sd2 += xk * (double)Wdel[(size_t)pj * DIM + k];
                    sh2 += hk * (double)__fmul_rn(Rh[(size_t)pj * DIM + k], s_h);
                    sv2 += hk * (double)__fmul_rn(Rd[(size_t)pj * DIM + k], s_d);
                }
                #pragma unroll
                for (int o = 16; o; o >>= 1) {
                    sa  += __shfl_down_sync(0xffffffffu, sa,  o);
                    sd2 += __shfl_down_sync(0xffffffffu, sd2, o);
                    sh2 += __shfl_down_sync(0xffffffffu, sh2, o);
                    sv2 += __shfl_down_sync(0xffffffffu, sv2, o);
                }
                if (l == 0) {
                    dred[w] = sa; dred[8 + w] = sd2; dred[16 + w] = sh2; dred[24 + w] = sv2;
                }
                __syncthreads();
                if (tid == 0) {
                    double A0 = 0, D0 = 0, H0 = 0, V0 = 0;
                    #pragma unroll
                    for (int i = 0; i < 8; i++) {
                        A0 += dred[i]; D0 += dred[8 + i]; H0 += dred[16 + i]; V0 += dred[24 + i];
                    }
                    double vv = A0 + H0 + (double)bj_s[plc];
                    double zz = D0 + V0 + (double)bdj_s[plc];
                    double cd = tanh(vv);
                    double dl = 1.0 / (1.0 + exp(-zz));
                    double hpd = (double)hb[pj];
                    double hnd = (1.0 - dl) * hpd + dl * cd;
                    float hnf = (float)hnd;
                    o_hlin[prow * DIM + pj] = hnf;
                    float lh2 = (float)log((double)fabsf(hnf) + 1e-12);
                    float sg2 = (hnf >= 0.f) ? 1.f : -1.f;
                    o_logh[(prow + BATCH) * DIM + pj] = lh2;
                    o_sign[(prow + BATCH) * DIM + pj] = sg2;
                    __stcg(&g_hbuf[(size_t)((t + 1) & 1) * (BATCH * DIM) + (size_t)pb * DIM + pj],
                           sg2 * (float)exp((double)lh2));
                }
                __syncthreads();
            }

            // ---- barrier: stores already ordered by the syncthreads above ----
            {
                unsigned sc = (unsigned)(t + 1);
                if (tid == 0) {
                    __threadfence();
                    *(volatile unsigned*)&g_flags[bid * 8] = sc;
                }
                if (bid == 0) {
                    if (tid < 128) {
                        volatile unsigned* fp = &g_flags[tid * 8];
                        while (*fp < sc) { }
                    }
                    __syncthreads();
                    if (tid == 0) {
                        __threadfence();
                        *(volatile unsigned*)&g_rel2 = sc;
                        __threadfence();
                    }
                } else {
                    if (tid == 0) {
                        volatile unsigned* rp = &g_rel2;
                        while (*rp < sc) { }      // hard spin: single shared line
                        __threadfence();
                    }
                }
                __syncthreads();
            }
        }
    } else {
        const int cb = bid - REC_CTAS;      // 0..CON_CTAS-1

        // ========== PHASE A: AD tiles for m-blocks PRO_MB..63 (m-block-major) ==========
        const int NTILES_A = (64 - PRO_MB) * 16;
        for (int q = cb; q < NTILES_A; q += CON_CTAS) {
            int mb = PRO_MB + (q >> 4);
            int nt = q & 15;
            ad_tile(x, Rx, Wdel, mb * 128, nt * 128, tid);
            __syncthreads();
            if (tid == 0) {
                __threadfence();
                atomicAdd(&g_mbcnt[mb], 1);
            }
            __syncthreads();
        }

        // ========== PHASE B: U = hlin @ Wout^T + fused compete ==========
        float* As2 = smem;
        float* Bs2 = smem + 2048;
        float* Ut  = smem + 4096;
        const int lr = tid >> 1;
        const int lk = (tid & 1) * 4;
        const int tx = tid & 15, ty = tid >> 4;
        const int w = tid >> 5, l = tid & 31;

        for (int ti = cb; ti < 512; ti += CON_CTAS) {
            int mb = ti >> 3;
            int nb = ti & 7;
            if (tid == 0) {
                volatile unsigned* rp = &g_rel2;
                unsigned need = (unsigned)((mb + 1) * 16);
                while (*rp < need) { __nanosleep(200); }
                __threadfence();
            }
            __syncthreads();

            const int m0 = mb * 128, n0 = nb * 128;
            const float* Aptr = o_hlin + (size_t)(m0 + lr) * DIM + lk;
            const float* Bptr = Wout   + (size_t)(n0 + lr) * DIM + lk;

            float acc[8][8];
            #pragma unroll
            for (int i = 0; i < 8; i++)
                #pragma unroll
                for (int j = 0; j < 8; j++) acc[i][j] = 0.f;

            float4 av = __ldcg((const float4*)Aptr);
            float4 bv = __ldcs((const float4*)Bptr);
            As2[(lk + 0) * 128 + lr] = av.x; As2[(lk + 1) * 128 + lr] = av.y;
            As2[(lk + 2) * 128 + lr] = av.z; As2[(lk + 3) * 128 + lr] = av.w;
            Bs2[(lk + 0) * 128 + lr] = bv.x; Bs2[(lk + 1) * 128 + lr] = bv.y;
            Bs2[(lk + 2) * 128 + lr] = bv.z; Bs2[(lk + 3) * 128 + lr] = bv.w;
            __syncthreads();

            int cur = 0;
            for (int k0 = 0; k0 < DIM; k0 += 8) {
                const bool more = (k0 + 8 < DIM);
                if (more) {
                    av = __ldcg((const float4*)(Aptr + k0 + 8));
                    bv = __ldcs((const float4*)(Bptr + k0 + 8));
                }
                float* Ac = As2 + cur * 1024;
                float* Bc = Bs2 + cur * 1024;
                #pragma unroll
                for (int kk = 0; kk < 8; kk++) {
                    float a[8], bb[8];
                    *(float4*)(a)      = *(const float4*)&Ac[kk * 128 + ty * 4];
                    *(float4*)(a + 4)  = *(const float4*)&Ac[kk * 128 + 64 + ty * 4];
                    *(float4*)(bb)     = *(const float4*)&Bc[kk * 128 + tx * 4];
                    *(float4*)(bb + 4) = *(const float4*)&Bc[kk * 128 + 64 + tx * 4];
                    #pragma unroll
                    for (int i = 0; i < 8; i++)
                        #pragma unroll
                        for (int j = 0; j < 8; j++)
                            acc[i][j] += a[i] * bb[j];
                }
                if (more) {
                    int nxt = 1 - cur;
                    float* An = As2 + nxt * 1024;
                    float* Bn = Bs2 + nxt * 1024;
                    An[(lk + 0) * 128 + lr] = av.x; An[(lk + 1) * 128 + lr] = av.y;
                    An[(lk + 2) * 128 + lr] = av.z; An[(lk + 3) * 128 + lr] = av.w;
                    Bn[(lk + 0) * 128 + lr] = bv.x; Bn[(lk + 1) * 128 + lr] = bv.y;
                    Bn[(lk + 2) * 128 + lr] = bv.z; Bn[(lk + 3) * 128 + lr] = bv.w;
                    __syncthreads();
                    cur = nxt;
                }
            }

            #pragma unroll
            for (int i = 0; i < 8; i++) {
                int rm = (i < 4) ? (ty * 4 + i) : (64 + ty * 4 + (i - 4));
                *(float4*)&Ut[rm * 128 + tx * 4]      = make_float4(acc[i][0], acc[i][1], acc[i][2], acc[i][3]);
                *(float4*)&Ut[rm * 128 + 64 + tx * 4] = make_float4(acc[i][4], acc[i][5], acc[i][6], acc[i][7]);
            }
            __syncthreads();

            for (int u = w; u < 512; u += 8) {
                int rm = u >> 2;
                int g  = u & 3;
                size_t m = (size_t)m0 + rm;
                int nl = g * 32 + l;
                float h = __ldcg(&o_hlin[m * DIM + n0 + nl]);
                float mx = h;
                #pragma unroll
                for (int o = 16; o; o >>= 1) mx = fmaxf(mx, __shfl_xor_sync(0xffffffffu, mx, o));
                float e = expf(h - mx);
                float sum = e;
                #pragma unroll
                for (int o = 16; o; o >>= 1) sum += __shfl_xor_sync(0xffffffffu, sum, o);
                float uv = Ut[rm * 128 + nl];
                float silu = uv / (1.f + expf(-uv));
                out[m * DIM + n0 + nl] = (e / sum) * silu;
            }
            __syncthreads();
        }
    }
}

extern "C" void kernel_launch(void* const* d_in, const int* in_sizes, int n_in,
                              void* d_out, int out_size) {
    const float* x      = (const float*)d_in[0];
    const float* logh0  = (const float*)d_in[1];
    const float* signh0 = (const float*)d_in[2];
    const float* Rh     = (const float*)d_in[3];
    const float* Rx     = (const float*)d_in[4];
    const float* Rd     = (const float*)d_in[5];
    const float* Wdel   = (const float*)d_in[6];
    const float* Wout   = (const float*)d_in[7];
    const float* bb     = (const float*)d_in[8];
    const float* bdel   = (const float*)d_in[9];
    const float* uh     = (const float*)d_in[10];
    const float* ud     = (const float*)d_in[11];

    float* out    = (float*)d_out;
    float* o_logh = out + (size_t)8388608;
    float* o_sign = out + (size_t)16785408;
    float* o_hlin = out + (size_t)25182208;

    cudaFuncSetAttribute(recurrence_kernel,
                         cudaFuncAttributeMaxDynamicSharedMemorySize, REC_SMEM);
    cudaFuncSetAttribute(sgemm_kernel,
                         cudaFuncAttributeMaxDynamicSharedMemorySize, 4096 * 4);

    init_kernel<<<32, 256>>>(logh0, signh0, o_logh, o_sign);
    spectral_kernel<<<64, 256>>>(Rh, Rd, uh, ud);
    sgemm_kernel<<<dim3(16, PRO_MB), 256, 4096 * 4>>>(x, Rx, Wdel);
    recurrence_kernel<<<REC_CTAS + CON_CTAS, 256, REC_SMEM>>>(
        Rh, Rd, x, Rx, Wdel, Wout, bb, bdel, o_hlin, o_logh, o_sign, out);
}

// round 14
// speedup vs baseline: 1.1048x; 1.1048x over previous
#include <cuda_runtime.h>
#include <cstdint>

#define T_STEPS   1024
#define BATCH     8
#define DIM       1024
#define MROWS     8192
#define REC_CTAS  128
#define CON_CTAS  24
#define PRO_MB    8          // m-blocks covered by prologue sgemm
#define REC_SMEM  ((16*1024 + 8*1024 + 256)*4)

__device__ __align__(16) float g_AD[(size_t)MROWS * 2048];
__device__ __align__(16) float g_hbuf[2 * BATCH * DIM];
__device__ float    g_scale[2];
__device__ __align__(16) double g_sud[2 * DIM];
__device__ __align__(16) double g_spartd[2 * 32 * DIM];
__device__ unsigned g_arrive;
__device__ unsigned g_release;
__device__ __align__(128) unsigned g_flags[128 * 8];
__device__ unsigned g_rel2;
__device__ int      g_mbcnt[64];     // per-m-block completed-tile counters (16 = ready)

// legacy barrier (spectral kernel only)
__device__ __forceinline__ void grid_barrier(unsigned relbase, unsigned nbar) {
    __syncthreads();
    if (threadIdx.x == 0) {
        __threadfence();
        unsigned a = atomicAdd(&g_arrive, 1u);
        if (a == gridDim.x - 1u) {
            atomicExch(&g_arrive, 0u);
            __threadfence();
            atomicAdd(&g_release, 1u);
        } else {
            volatile unsigned* rel = &g_release;
            while ((unsigned)(*rel - relbase) < nbar) { __nanosleep(40); }
        }
        __threadfence();
    }
    __syncthreads();
}

__device__ __forceinline__ double block_reduce_sum_d(double v, double* red) {
    __syncthreads();
    int lane = threadIdx.x & 31, w = threadIdx.x >> 5;
    #pragma unroll
    for (int o = 16; o; o >>= 1) v += __shfl_xor_sync(0xffffffffu, v, o);
    if (lane == 0) red[w] = v;
    __syncthreads();
    if (threadIdx.x == 0) {
        double t = 0.0;
        #pragma unroll
        for (int i = 0; i < 8; i++) t += red[i];
        red[0] = t;
    }
    __syncthreads();
    return red[0];
}

// ============ spectral norm in DOUBLE (unchanged) ============
__global__ void spectral_kernel(const float* __restrict__ Rh, const float* __restrict__ Rd,
                                const float* __restrict__ uh, const float* __restrict__ ud) {
    const int m = blockIdx.x >> 5;
    const int r = blockIdx.x & 31;
    const float* W  = m ? Rd : Rh;
    const float* u0 = m ? ud : uh;
    double* gu    = g_sud    + m * DIM;
    double* gpart = g_spartd + (size_t)m * 32 * DIM;
    const int tid = threadIdx.x;

    __shared__ double red[16];
    __shared__ double v_s[DIM];
    __shared__ unsigned sh_rb;
    if (tid == 0) sh_rb = *(volatile unsigned*)&g_release;
    __syncthreads();
    const unsigned relbase = sh_rb;
    unsigned nbar = 0;

    double ss = 0.0;
    for (int i = tid; i < DIM; i += 256) { double v = (double)u0[i]; ss += v * v; }
    ss = block_reduce_sum_d(ss, red);
    double inv_u = 1.0 / (sqrt(ss) + 1e-8);

    int use_u0 = 1;
    double S_last = 0.0;

    for (int it = 0; it < 3; it++) {
        double a0 = 0, a1 = 0, a2 = 0, a3 = 0;
        for (int kk = 0; kk < 32; kk++) {
            int k = r * 32 + kk;
            double uk = (use_u0 ? (double)u0[k] : gu[k]) * inv_u;
            float4 wv = *(const float4*)(W + (size_t)k * DIM + tid * 4);
            a0 += (double)wv.x * uk; a1 += (double)wv.y * uk;
            a2 += (double)wv.z * uk; a3 += (double)wv.w * uk;
        }
        double* pdst = gpart + (size_t)r * DIM + tid * 4;
        pdst[0] = a0; pdst[1] = a1; pdst[2] = a2; pdst[3] = a3;
        grid_barrier(relbase, ++nbar);

        double s0 = 0, s1 = 0, s2 = 0, s3 = 0;
        for (int rr = 0; rr < 32; rr++) {
            const double* p = gpart + (size_t)rr * DIM + tid * 4;
            s0 += p[0]; s1 += p[1]; s2 += p[2]; s3 += p[3];
        }
        v_s[tid * 4 + 0] = s0; v_s[tid * 4 + 1] = s1;
        v_s[tid * 4 + 2] = s2; v_s[tid * 4 + 3] = s3;
        double ssv = s0 * s0 + s1 * s1 + s2 * s2 + s3 * s3;
        ssv = block_reduce_sum_d(ssv, red);
        double inv_v = 1.0 / (sqrt(ssv) + 1e-8);

        {
            int wnum = tid >> 5, lane = tid & 31;
            for (int rr = 0; rr < 4; rr++) {
                int row = r * 32 + wnum * 4 + rr;
                double p = 0.0;
                for (int k = lane; k < DIM; k += 32)
                    p += (double)W[(size_t)row * DIM + k] * v_s[k];
                #pragma unroll
                for (int o = 16; o; o >>= 1) p += __shfl_down_sync(0xffffffffu, p, o);
                if (lane == 0) gu[row] = p * inv_v;
            }
        }
        grid_barrier(relbase, ++nbar);

        double s2sum = 0.0;
        for (int i = tid; i < DIM; i += 256) { double v = gu[i]; s2sum += v * v; }
        s2sum = block_reduce_sum_d(s2sum, red);
        inv_u = 1.0 / (sqrt(s2sum) + 1e-8);
        S_last = s2sum;
        use_u0 = 0;
    }

    double sigma = S_last / sqrt(S_last);
    if (r == 0 && tid == 0) g_scale[m] = (float)(0.99 / (sigma + 1e-8));
}

// ============ shared double-buffered 128x128 AD tile body (bit-exact chains) ============
__device__ __forceinline__ void ad_tile(
    const float* __restrict__ x, const float* __restrict__ Rx,
    const float* __restrict__ Wdel, int m0, int n0, int tid) {

    extern __shared__ float smem[];
    float* As = smem;            // [2][8][128]
    float* Bs = smem + 2048;     // [2][8][128]

    const float* B; int nb;
    if (n0 < DIM) { B = Rx; nb = n0; }
    else          { B = Wdel; nb = n0 - DIM; }

    const int lr = tid >> 1;
    const int lk = (tid & 1) * 4;
    const int tx = tid & 15, ty = tid >> 4;

    float acc[8][8];
    #pragma unroll
    for (int i = 0; i < 8; i++)
        #pragma unroll
        for (int j = 0; j < 8; j++) acc[i][j] = 0.f;

    const float* Aptr = x + (size_t)(m0 + lr) * DIM + lk;
    const float* Bptr = B + (size_t)(nb + lr) * DIM + lk;

    float4 av = *(const float4*)(Aptr);
    float4 bv = *(const float4*)(Bptr);
    As[(lk + 0) * 128 + lr] = av.x; As[(lk + 1) * 128 + lr] = av.y;
    As[(lk + 2) * 128 + lr] = av.z; As[(lk + 3) * 128 + lr] = av.w;
    Bs[(lk + 0) * 128 + lr] = bv.x; Bs[(lk + 1) * 128 + lr] = bv.y;
    Bs[(lk + 2) * 128 + lr] = bv.z; Bs[(lk + 3) * 128 + lr] = bv.w;
    __syncthreads();

    int cur = 0;
    for (int k0 = 0; k0 < DIM; k0 += 8) {
        const bool more = (k0 + 8 < DIM);
        if (more) {
            av = *(const float4*)(Aptr + k0 + 8);
            bv = *(const float4*)(Bptr + k0 + 8);
        }
        float* Ac = As + cur * 1024;
        float* Bc = Bs + cur * 1024;
        #pragma unroll
        for (int kk = 0; kk < 8; kk++) {
            float a[8], bb[8];
            *(float4*)(a)      = *(const float4*)&Ac[kk * 128 + ty * 4];
            *(float4*)(a + 4)  = *(const float4*)&Ac[kk * 128 + 64 + ty * 4];
            *(float4*)(bb)     = *(const float4*)&Bc[kk * 128 + tx * 4];
            *(float4*)(bb + 4) = *(const float4*)&Bc[kk * 128 + 64 + tx * 4];
            #pragma unroll
            for (int i = 0; i < 8; i++)
                #pragma unroll
                for (int j = 0; j < 8; j++)
                    acc[i][j] += a[i] * bb[j];
        }
        if (more) {
            int nxt = 1 - cur;
            float* An = As + nxt * 1024;
            float* Bn = Bs + nxt * 1024;
            An[(lk + 0) * 128 + lr] = av.x; An[(lk + 1) * 128 + lr] = av.y;
            An[(lk + 2) * 128 + lr] = av.z; An[(lk + 3) * 128 + lr] = av.w;
            Bn[(lk + 0) * 128 + lr] = bv.x; Bn[(lk + 1) * 128 + lr] = bv.y;
            Bn[(lk + 2) * 128 + lr] = bv.z; Bn[(lk + 3) * 128 + lr] = bv.w;
            __syncthreads();
            cur = nxt;
        }
    }

    #pragma unroll
    for (int i = 0; i < 8; i++) {
        int m = m0 + ((i < 4) ? (ty * 4 + i) : (64 + ty * 4 + (i - 4)));
        float4 c0 = make_float4(acc[i][0], acc[i][1], acc[i][2], acc[i][3]);
        float4 c1 = make_float4(acc[i][4], acc[i][5], acc[i][6], acc[i][7]);
        *(float4*)(g_AD + (size_t)m * 2048 + n0 + tx * 4)      = c0;
        *(float4*)(g_AD + (size_t)m * 2048 + n0 + 64 + tx * 4) = c1;
    }
}

// ============ prologue sgemm: m-blocks 0..PRO_MB-1 ============
__global__ void __launch_bounds__(256) sgemm_kernel(
    const float* __restrict__ x, const float* __restrict__ Rx,
    const float* __restrict__ Wdel) {
    ad_tile(x, Rx, Wdel, blockIdx.y * 128, blockIdx.x * 128, threadIdx.x);
}

// ============ init ============
__global__ void init_kernel(const float* __restrict__ logh0, const float* __restrict__ signh0,
                            float* __restrict__ o_logh, float* __restrict__ o_sign) {
    int i = blockIdx.x * 256 + threadIdx.x;
    float lh = logh0[i], s = signh0[i];
    o_logh[i] = lh;
    o_sign[i] = s;
    g_hbuf[i] = s * expf(lh);
    if (i < 128 * 8) g_flags[i] = 0u;
    if (i < 64) g_mbcnt[i] = 0;
    if (i == 0) { g_rel2 = 0u; g_arrive = 0u; g_release = 0u; }
}

// ============ combined: 0-127 recurrence, 128+ producer(AD) then consumer(U+compete) ============
__global__ void __launch_bounds__(256) recurrence_kernel(
    const float* __restrict__ Rh, const float* __restrict__ Rd,
    const float* __restrict__ x,  const float* __restrict__ Rx,
    const float* __restrict__ Wdel, const float* __restrict__ Wout,
    const float* __restrict__ bvec, const float* __restrict__ bdel,
    float* __restrict__ o_hlin, float* __restrict__ o_logh, float* __restrict__ o_sign,
    float* __restrict__ out) {

    extern __shared__ float smem[];
    const int tid = threadIdx.x;
    const int bid = blockIdx.x;

    if (bid < REC_CTAS) {
        // ================= RECURRENCE ROLE (R12-verbatim) =================
        float* W_s  = smem;
        float* h_s  = smem + 16 * 1024;
        float* part = smem + 16 * 1024 + 8 * 1024;
        const int j0  = bid * 8;

        __shared__ float bj_s[8], bdj_s[8];
        __shared__ double ds[64];
        __shared__ int   flag_n;
        __shared__ int   flag_pos[16];
        __shared__ double dred[32];
        if (tid < 8)       bj_s[tid]  = bvec[j0 + tid];
        else if (tid < 16) bdj_s[tid - 8] = bdel[j0 + tid - 8];

        const float s_h = g_scale[0];
        const float s_d = g_scale[1];

        for (int idx = tid; idx < 2048; idx += 256) {
            int row = idx >> 8;
            int c4  = idx & 255;
            float4 a = *(const float4*)(Rh + (size_t)(j0 + row) * DIM + c4 * 4);
            a.x *= s_h; a.y *= s_h; a.z *= s_h; a.w *= s_h;
            ((float4*)(W_s + (size_t)row * DIM))[c4] = a;
            float4 d = *(const float4*)(Rd + (size_t)(j0 + row) * DIM + c4 * 4);
            d.x *= s_d; d.y *= s_d; d.z *= s_d; d.w *= s_d;
            ((float4*)(W_s + (size_t)(8 + row) * DIM))[c4] = d;
        }
        __syncthreads();

        const int w  = tid >> 5, l = tid & 31;
        const int kh = w >> 2;
        const int cg = (w & 3) << 2;
        const int ei  = tid & 63;
        const int elc = ei >> 3, eb = ei & 7;

        for (int t = 0; t < T_STEPS; t++) {
            if ((t & 15) == 0 && t >= PRO_MB * 16) {
                volatile int* c = &g_mbcnt[t >> 4];
                while (*c < 16) { }
            }

            float ad_pf = 0.f;
            {
                size_t prow = (size_t)t * BATCH + eb;
                if (tid < 64)       ad_pf = __ldcg(&g_AD[prow * 2048 + j0 + elc]);
                else if (tid < 128) ad_pf = __ldcg(&g_AD[prow * 2048 + 1024 + j0 + elc]);
            }
            if (tid == 0) flag_n = 0;

            const float* hsrc = g_hbuf + (size_t)(t & 1) * (BATCH * DIM);
            for (int i = tid; i < 2048; i += 256)
                ((float4*)h_s)[i] = __ldcg(((const float4*)hsrc) + i);
            __syncthreads();

            float acc[4][8];
            #pragma unroll
            for (int c = 0; c < 4; c++)
                #pragma unroll
                for (int b = 0; b < 8; b++) acc[c][b] = 0.f;

            #pragma unroll
            for (int i = 0; i < 4; i++) {
                int kb = (kh << 9) + (i << 7) + (l << 2);
                float4 w4[4];
                #pragma unroll
                for (int c = 0; c < 4; c++)
                    w4[c] = *(const float4*)(W_s + (size_t)(cg + c) * DIM + kb);
                #pragma unroll
                for (int b = 0; b < 8; b++) {
                    float4 h4 = *(const float4*)(h_s + (size_t)b * DIM + kb);
                    #pragma unroll
                    for (int c = 0; c < 4; c++)
                        acc[c][b] += w4[c].x * h4.x + w4[c].y * h4.y
                                   + w4[c].z * h4.z + w4[c].w * h4.w;
                }
            }
            #pragma unroll
            for (int o = 16; o; o >>= 1)
                #pragma unroll
                for (int c = 0; c < 4; c++)
                    #pragma unroll
                    for (int b = 0; b < 8; b++)
                        acc[c][b] += __shfl_down_sync(0xffffffffu, acc[c][b], o);
            if (l == 0) {
                #pragma unroll
                for (int c = 0; c < 4; c++)
                    #pragma unroll
                    for (int b = 0; b < 8; b++)
                        part[(cg + c) * 16 + b * 2 + kh] = acc[c][b];
            }
            __syncthreads();

            double cand_r = 0.0;
            if (tid < 64) {
                double hv = (double)part[elc * 16 + eb * 2 + 0] + (double)part[elc * 16 + eb * 2 + 1];
                cand_r = tanh((double)ad_pf + hv + (double)bj_s[elc]);
            } else if (tid < 128) {
                double dv = (double)part[(8 + elc) * 16 + eb * 2 + 0] + (double)part[(8 + elc) * 16 + eb * 2 + 1];
                ds[ei] = 1.0 / (1.0 + exp(-((double)ad_pf + dv + (double)bdj_s[elc])));
            }
            if (tid < 128)
                asm volatile("bar.sync 1, 128;" ::: "memory");

            if (tid < 64) {
                int j = j0 + elc;
                size_t row = (size_t)t * BATCH + eb;
                double delta = ds[ei];
                double hp = (double)h_s[(size_t)eb * DIM + j];
                double hnd = (1.0 - delta) * hp + delta * cand_r;
                float hn = (float)hnd;
                float lh = (float)log((double)fabsf(hn) + 1e-12);
                float sg = (hn >= 0.f) ? 1.f : -1.f;
                __stcg(&g_hbuf[(size_t)((t + 1) & 1) * (BATCH * DIM) + (size_t)eb * DIM + j],
                       sg * (float)exp((double)lh));
                o_hlin[row * DIM + j] = hn;
                o_logh[(row + BATCH) * DIM + j] = lh;
                o_sign[(row + BATCH) * DIM + j] = sg;
                if (fabsf(hn) < 4e-6f) {
                    int fi = atomicAdd(&flag_n, 1);
                    if (fi < 16) flag_pos[fi] = (eb << 16) | elc;
                }
            }
            __syncthreads();

            int nf = flag_n; if (nf > 16) nf = 16;
            for (int f = 0; f < nf; f++) {
                int pb  = flag_pos[f] >> 16;
                int plc = flag_pos[f] & 0xffff;
                int pj  = j0 + plc;
                size_t prow = (size_t)t * BATCH + pb;
                const float* xr = x + prow * DIM;
                const float* hb = h_s + (size_t)pb * DIM;
                double sa = 0, sd2 = 0, sh2 = 0, sv2 = 0;
                for (int k = tid; k < DIM; k += 256) {
                    double xk = (double)xr[k], hk = (double)hb[k];
                    sa  += xk * (double)Rx  [(size_t)pj * DIM + k];
                    sd2 += xk * (double)Wdel[(size_t)pj * DIM + k];
                    sh2 += hk * (double)__fmul_rn(Rh[(size_t)pj * DIM + k], s_h);
                    sv2 += hk * (double)__fmul_rn(Rd[(size_t)pj * DIM + k], s_d);
                }
                #pragma unroll
                for (int o = 16; o; o >>= 1) {
                    sa  += __shfl_down_sync(0xffffffffu, sa,  o);
                    sd2 += __shfl_down_sync(0xffffffffu, sd2, o);
                    sh2 += __shfl_down_sync(0xffffffffu, sh2, o);
                    sv2 += __shfl_down_sync(0xffffffffu, sv2, o);
                }
                if (l == 0) {
                    dred[w] = sa; dred[8 + w] = sd2; dred[16 + w] = sh2; dred[24 + w] = sv2;
                }
                __syncthreads();
                if (tid == 0) {
                    double A0 = 0, D0 = 0, H0 = 0, V0 = 0;
                    #pragma unroll
                    for (int i = 0; i < 8; i++) {
                        A0 += dred[i]; D0 += dred[8 + i]; H0 += dred[16 + i]; V0 += dred[24 + i];
                    }
                    double vv = A0 + H0 + (double)bj_s[plc];
                    double zz = D0 + V0 + (double)bdj_s[plc];
                    double cd = tanh(vv);
                    double dl = 1.0 / (1.0 + exp(-zz));
                    double hpd = (double)hb[pj];
                    double hnd = (1.0 - dl) * hpd + dl * cd;
                    float hnf = (float)hnd;
                    o_hlin[prow * DIM + pj] = hnf;
                    float lh2 = (float)log((double)fabsf(hnf) + 1e-12);
                    float sg2 = (hnf >= 0.f) ? 1.f : -1.f;
                    o_logh[(prow + BATCH) * DIM + pj] = lh2;
                    o_sign[(prow + BATCH) * DIM + pj] = sg2;
                    __stcg(&g_hbuf[(size_t)((t + 1) & 1) * (BATCH * DIM) + (size_t)pb * DIM + pj],
                           sg2 * (float)exp((double)lh2));
                }
                __syncthreads();
            }

            {
                unsigned sc = (unsigned)(t + 1);
                __syncthreads();
                if (tid == 0) {
                    __threadfence();
                    *(volatile unsigned*)&g_flags[bid * 8] = sc;
                }
                if (bid == 0) {
                    if (tid < 128) {
                        volatile unsigned* fp = &g_flags[tid * 8];
                        while (*fp < sc) { }
                    }
                    __syncthreads();
                    if (tid == 0) {
                        __threadfence();
                        *(volatile unsigned*)&g_rel2 = sc;
                        __threadfence();
                    }
                } else {
                    if (tid == 0) {
                        volatile unsigned* rp = &g_rel2;
                        while (*rp < sc) { __nanosleep(30); }
                        __threadfence();
                    }
                }
                __syncthreads();
            }
        }
    } else {
        const int cb = bid - REC_CTAS;      // 0..CON_CTAS-1

        // ========== PHASE A (producer): AD tiles for m-blocks PRO_MB..63 ==========
        const int NTILES_A = (64 - PRO_MB) * 16;   // 896
        for (int q = cb; q < NTILES_A; q += CON_CTAS) {
            int mb = PRO_MB + (q >> 4);
            int nt = q & 15;
            ad_tile(x, Rx, Wdel, mb * 128, nt * 128, tid);
            __syncthreads();
            if (tid == 0) {
                __threadfence();
                atomicAdd(&g_mbcnt[mb], 1);
            }
            __syncthreads();
        }

        // ========== PHASE B (consumer): U = hlin @ Wout^T + fused compete ==========
        float* As2 = smem;
        float* Bs2 = smem + 2048;
        float* Ut  = smem + 4096;
        const int lr = tid >> 1;
        const int lk = (tid & 1) * 4;
        const int tx = tid & 15, ty = tid >> 4;
        const int w = tid >> 5, l = tid & 31;

        for (int ti = cb; ti < 512; ti += CON_CTAS) {
            int mb = ti >> 3;
            int nb = ti & 7;
            if (tid == 0) {
                volatile unsigned* rp = &g_rel2;
                unsigned need = (unsigned)((mb + 1) * 16);
                while (*rp < need) { __nanosleep(200); }
                __threadfence();
            }
            __syncthreads();

            const int m0 = mb * 128, n0 = nb * 128;
            const float* Aptr = o_hlin + (size_t)(m0 + lr) * DIM + lk;
            const float* Bptr = Wout   + (size_t)(n0 + lr) * DIM + lk;

            float acc[8][8];
            #pragma unroll
            for (int i = 0; i < 8; i++)
                #pragma unroll
                for (int j = 0; j < 8; j++) acc[i][j] = 0.f;

            float4 av = __ldcg((const float4*)Aptr);
            float4 bv = *(const float4*)Bptr;
            As2[(lk + 0) * 128 + lr] = av.x; As2[(lk + 1) * 128 + lr] = av.y;
            As2[(lk + 2) * 128 + lr] = av.z; As2[(lk + 3) * 128 + lr] = av.w;
            Bs2[(lk + 0) * 128 + lr] = bv.x; Bs2[(lk + 1) * 128 + lr] = bv.y;
            Bs2[(lk + 2) * 128 + lr] = bv.z; Bs2[(lk + 3) * 128 + lr] = bv.w;
            __syncthreads();

            int cur = 0;
            for (int k0 = 0; k0 < DIM; k0 += 8) {
                const bool more = (k0 + 8 < DIM);
                if (more) {
                    av = __ldcg((const float4*)(Aptr + k0 + 8));
                    bv = *(const float4*)(Bptr + k0 + 8);
                }
                float* Ac = As2 + cur * 1024;
                float* Bc = Bs2 + cur * 1024;
                #pragma unroll
                for (int kk = 0; kk < 8; kk++) {
                    float a[8], bb[8];
                    *(float4*)(a)      = *(const float4*)&Ac[kk * 128 + ty * 4];
                    *(float4*)(a + 4)  = *(const float4*)&Ac[kk * 128 + 64 + ty * 4];
                    *(float4*)(bb)     = *(const float4*)&Bc[kk * 128 + tx * 4];
                    *(float4*)(bb + 4) = *(const float4*)&Bc[kk * 128 + 64 + tx * 4];
                    #pragma unroll
                    for (int i = 0; i < 8; i++)
                        #pragma unroll
                        for (int j = 0; j < 8; j++)
                            acc[i][j] += a[i] * bb[j];
                }
                if (more) {
                    int nxt = 1 - cur;
                    float* An = As2 + nxt * 1024;
                    float* Bn = Bs2 + nxt * 1024;
                    An[(lk + 0) * 128 + lr] = av.x; An[(lk + 1) * 128 + lr] = av.y;
                    An[(lk + 2) * 128 + lr] = av.z; An[(lk + 3) * 128 + lr] = av.w;
                    Bn[(lk + 0) * 128 + lr] = bv.x; Bn[(lk + 1) * 128 + lr] = bv.y;
                    Bn[(lk + 2) * 128 + lr] = bv.z; Bn[(lk + 3) * 128 + lr] = bv.w;
                    __syncthreads();
                    cur = nxt;
                }
            }

            #pragma unroll
            for (int i = 0; i < 8; i++) {
                int rm = (i < 4) ? (ty * 4 + i) : (64 + ty * 4 + (i - 4));
                *(float4*)&Ut[rm * 128 + tx * 4]      = make_float4(acc[i][0], acc[i][1], acc[i][2], acc[i][3]);
                *(float4*)&Ut[rm * 128 + 64 + tx * 4] = make_float4(acc[i][4], acc[i][5], acc[i][6], acc[i][7]);
            }
            __syncthreads();

            for (int u = w; u < 512; u += 8) {
                int rm = u >> 2;
                int g  = u & 3;
                size_t m = (size_t)m0 + rm;
                int nl = g * 32 + l;
                float h = __ldcg(&o_hlin[m * DIM + n0 + nl]);
                float mx = h;
                #pragma unroll
                for (int o = 16; o; o >>= 1) mx = fmaxf(mx, __shfl_xor_sync(0xffffffffu, mx, o));
                float e = expf(h - mx);
                float sum = e;
                #pragma unroll
                for (int o = 16; o; o >>= 1) sum += __shfl_xor_sync(0xffffffffu, sum, o);
                float uv = Ut[rm * 128 + nl];
                float silu = uv / (1.f + expf(-uv));
                out[m * DIM + n0 + nl] = (e / sum) * silu;
            }
            __syncthreads();
        }
    }
}

extern "C" void kernel_launch(void* const* d_in, const int* in_sizes, int n_in,
                              void* d_out, int out_size) {
    const float* x      = (const float*)d_in[0];
    const float* logh0  = (const float*)d_in[1];
    const float* signh0 = (const float*)d_in[2];
    const float* Rh     = (const float*)d_in[3];
    const float* Rx     = (const float*)d_in[4];
    const float* Rd     = (const float*)d_in[5];
    const float* Wdel   = (const float*)d_in[6];
    const float* Wout   = (const float*)d_in[7];
    const float* bb     = (const float*)d_in[8];
    const float* bdel   = (const float*)d_in[9];
    const float* uh     = (const float*)d_in[10];
    const float* ud     = (const float*)d_in[11];

    float* out    = (float*)d_out;
    float* o_logh = out + (size_t)8388608;
    float* o_sign = out + (size_t)16785408;
    float* o_hlin = out + (size_t)25182208;

    cudaFuncSetAttribute(recurrence_kernel,
                         cudaFuncAttributeMaxDynamicSharedMemorySize, REC_SMEM);
    cudaFuncSetAttribute(sgemm_kernel,
                         cudaFuncAttributeMaxDynamicSharedMemorySize, 4096 * 4);

    init_kernel<<<32, 256>>>(logh0, signh0, o_logh, o_sign);
    spectral_kernel<<<64, 256>>>(Rh, Rd, uh, ud);
    sgemm_kernel<<<dim3(16, PRO_MB), 256, 4096 * 4>>>(x, Rx, Wdel);
    recurrence_kernel<<<REC_CTAS + CON_CTAS, 256, REC_SMEM>>>(
        Rh, Rd, x, Rx, Wdel, Wout, bb, bdel, o_hlin, o_logh, o_sign, out);
}

// round 15
// speedup vs baseline: 1.2270x; 1.1106x over previous
#include <cuda_runtime.h>
#include <cstdint>

#define T_STEPS   1024
#define BATCH     8
#define DIM       1024
#define MROWS     8192
#define REC_CTAS  128
#define CON_CTAS  24
#define PRO_MB    8
#define REC_SMEM  ((16*1024 + 8*1024 + 256)*4)

__device__ __align__(16) float g_AD[(size_t)MROWS * 2048];
__device__ __align__(16) float g_hbuf[2 * BATCH * DIM];
__device__ float    g_scale[2];
__device__ __align__(16) double g_sud[2 * DIM];
__device__ __align__(16) double g_spartd[2 * 32 * DIM];
__device__ unsigned g_arrive;
__device__ unsigned g_release;
__device__ __align__(128) unsigned g_cnt;      // monotone arrival counter (one-leg barrier)
__device__ int      g_mbcnt[64];

// legacy barrier (spectral kernel only)
__device__ __forceinline__ void grid_barrier(unsigned relbase, unsigned nbar) {
    __syncthreads();
    if (threadIdx.x == 0) {
        __threadfence();
        unsigned a = atomicAdd(&g_arrive, 1u);
        if (a == gridDim.x - 1u) {
            atomicExch(&g_arrive, 0u);
            __threadfence();
            atomicAdd(&g_release, 1u);
        } else {
            volatile unsigned* rel = &g_release;
            while ((unsigned)(*rel - relbase) < nbar) { __nanosleep(40); }
        }
        __threadfence();
    }
    __syncthreads();
}

__device__ __forceinline__ double block_reduce_sum_d(double v, double* red) {
    __syncthreads();
    int lane = threadIdx.x & 31, w = threadIdx.x >> 5;
    #pragma unroll
    for (int o = 16; o; o >>= 1) v += __shfl_xor_sync(0xffffffffu, v, o);
    if (lane == 0) red[w] = v;
    __syncthreads();
    if (threadIdx.x == 0) {
        double t = 0.0;
        #pragma unroll
        for (int i = 0; i < 8; i++) t += red[i];
        red[0] = t;
    }
    __syncthreads();
    return red[0];
}

// ============ spectral norm in DOUBLE (unchanged) ============
__global__ void spectral_kernel(const float* __restrict__ Rh, const float* __restrict__ Rd,
                                const float* __restrict__ uh, const float* __restrict__ ud) {
    const int m = blockIdx.x >> 5;
    const int r = blockIdx.x & 31;
    const float* W  = m ? Rd : Rh;
    const float* u0 = m ? ud : uh;
    double* gu    = g_sud    + m * DIM;
    double* gpart = g_spartd + (size_t)m * 32 * DIM;
    const int tid = threadIdx.x;

    __shared__ double red[16];
    __shared__ double v_s[DIM];
    __shared__ unsigned sh_rb;
    if (tid == 0) sh_rb = *(volatile unsigned*)&g_release;
    __syncthreads();
    const unsigned relbase = sh_rb;
    unsigned nbar = 0;

    double ss = 0.0;
    for (int i = tid; i < DIM; i += 256) { double v = (double)u0[i]; ss += v * v; }
    ss = block_reduce_sum_d(ss, red);
    double inv_u = 1.0 / (sqrt(ss) + 1e-8);

    int use_u0 = 1;
    double S_last = 0.0;

    for (int it = 0; it < 3; it++) {
        double a0 = 0, a1 = 0, a2 = 0, a3 = 0;
        for (int kk = 0; kk < 32; kk++) {
            int k = r * 32 + kk;
            double uk = (use_u0 ? (double)u0[k] : gu[k]) * inv_u;
            float4 wv = *(const float4*)(W + (size_t)k * DIM + tid * 4);
            a0 += (double)wv.x * uk; a1 += (double)wv.y * uk;
            a2 += (double)wv.z * uk; a3 += (double)wv.w * uk;
        }
        double* pdst = gpart + (size_t)r * DIM + tid * 4;
        pdst[0] = a0; pdst[1] = a1; pdst[2] = a2; pdst[3] = a3;
        grid_barrier(relbase, ++nbar);

        double s0 = 0, s1 = 0, s2 = 0, s3 = 0;
        for (int rr = 0; rr < 32; rr++) {
            const double* p = gpart + (size_t)rr * DIM + tid * 4;
            s0 += p[0]; s1 += p[1]; s2 += p[2]; s3 += p[3];
        }
        v_s[tid * 4 + 0] = s0; v_s[tid * 4 + 1] = s1;
        v_s[tid * 4 + 2] = s2; v_s[tid * 4 + 3] = s3;
        double ssv = s0 * s0 + s1 * s1 + s2 * s2 + s3 * s3;
        ssv = block_reduce_sum_d(ssv, red);
        double inv_v = 1.0 / (sqrt(ssv) + 1e-8);

        {
            int wnum = tid >> 5, lane = tid & 31;
            for (int rr = 0; rr < 4; rr++) {
                int row = r * 32 + wnum * 4 + rr;
                double p = 0.0;
                for (int k = lane; k < DIM; k += 32)
                    p += (double)W[(size_t)row * DIM + k] * v_s[k];
                #pragma unroll
                for (int o = 16; o; o >>= 1) p += __shfl_down_sync(0xffffffffu, p, o);
                if (lane == 0) gu[row] = p * inv_v;
            }
        }
        grid_barrier(relbase, ++nbar);

        double s2sum = 0.0;
        for (int i = tid; i < DIM; i += 256) { double v = gu[i]; s2sum += v * v; }
        s2sum = block_reduce_sum_d(s2sum, red);
        inv_u = 1.0 / (sqrt(s2sum) + 1e-8);
        S_last = s2sum;
        use_u0 = 0;
    }

    double sigma = S_last / sqrt(S_last);
    if (r == 0 && tid == 0) g_scale[m] = (float)(0.99 / (sigma + 1e-8));
}

// ============ shared double-buffered 128x128 AD tile body (bit-exact chains) ============
__device__ __forceinline__ void ad_tile(
    const float* __restrict__ x, const float* __restrict__ Rx,
    const float* __restrict__ Wdel, int m0, int n0, int tid) {

    extern __shared__ float smem[];
    float* As = smem;
    float* Bs = smem + 2048;

    const float* B; int nb;
    if (n0 < DIM) { B = Rx; nb = n0; }
    else          { B = Wdel; nb = n0 - DIM; }

    const int lr = tid >> 1;
    const int lk = (tid & 1) * 4;
    const int tx = tid & 15, ty = tid >> 4;

    float acc[8][8];
    #pragma unroll
    for (int i = 0; i < 8; i++)
        #pragma unroll
        for (int j = 0; j < 8; j++) acc[i][j] = 0.f;

    const float* Aptr = x + (size_t)(m0 + lr) * DIM + lk;
    const float* Bptr = B + (size_t)(nb + lr) * DIM + lk;

    float4 av = *(const float4*)(Aptr);
    float4 bv = *(const float4*)(Bptr);
    As[(lk + 0) * 128 + lr] = av.x; As[(lk + 1) * 128 + lr] = av.y;
    As[(lk + 2) * 128 + lr] = av.z; As[(lk + 3) * 128 + lr] = av.w;
    Bs[(lk + 0) * 128 + lr] = bv.x; Bs[(lk + 1) * 128 + lr] = bv.y;
    Bs[(lk + 2) * 128 + lr] = bv.z; Bs[(lk + 3) * 128 + lr] = bv.w;
    __syncthreads();

    int cur = 0;
    for (int k0 = 0; k0 < DIM; k0 += 8) {
        const bool more = (k0 + 8 < DIM);
        if (more) {
            av = *(const float4*)(Aptr + k0 + 8);
            bv = *(const float4*)(Bptr + k0 + 8);
        }
        float* Ac = As + cur * 1024;
        float* Bc = Bs + cur * 1024;
        #pragma unroll
        for (int kk = 0; kk < 8; kk++) {
            float a[8], bb[8];
            *(float4*)(a)      = *(const float4*)&Ac[kk * 128 + ty * 4];
            *(float4*)(a + 4)  = *(const float4*)&Ac[kk * 128 + 64 + ty * 4];
            *(float4*)(bb)     = *(const float4*)&Bc[kk * 128 + tx * 4];
            *(float4*)(bb + 4) = *(const float4*)&Bc[kk * 128 + 64 + tx * 4];
            #pragma unroll
            for (int i = 0; i < 8; i++)
                #pragma unroll
                for (int j = 0; j < 8; j++)
                    acc[i][j] += a[i] * bb[j];
        }
        if (more) {
            int nxt = 1 - cur;
            float* An = As + nxt * 1024;
            float* Bn = Bs + nxt * 1024;
            An[(lk + 0) * 128 + lr] = av.x; An[(lk + 1) * 128 + lr] = av.y;
            An[(lk + 2) * 128 + lr] = av.z; An[(lk + 3) * 128 + lr] = av.w;
            Bn[(lk + 0) * 128 + lr] = bv.x; Bn[(lk + 1) * 128 + lr] = bv.y;
            Bn[(lk + 2) * 128 + lr] = bv.z; Bn[(lk + 3) * 128 + lr] = bv.w;
            __syncthreads();
            cur = nxt;
        }
    }

    #pragma unroll
    for (int i = 0; i < 8; i++) {
        int m = m0 + ((i < 4) ? (ty * 4 + i) : (64 + ty * 4 + (i - 4)));
        float4 c0 = make_float4(acc[i][0], acc[i][1], acc[i][2], acc[i][3]);
        float4 c1 = make_float4(acc[i][4], acc[i][5], acc[i][6], acc[i][7]);
        *(float4*)(g_AD + (size_t)m * 2048 + n0 + tx * 4)      = c0;
        *(float4*)(g_AD + (size_t)m * 2048 + n0 + 64 + tx * 4) = c1;
    }
}

__global__ void __launch_bounds__(256) sgemm_kernel(
    const float* __restrict__ x, const float* __restrict__ Rx,
    const float* __restrict__ Wdel) {
    ad_tile(x, Rx, Wdel, blockIdx.y * 128, blockIdx.x * 128, threadIdx.x);
}

__global__ void init_kernel(const float* __restrict__ logh0, const float* __restrict__ signh0,
                            float* __restrict__ o_logh, float* __restrict__ o_sign) {
    int i = blockIdx.x * 256 + threadIdx.x;
    float lh = logh0[i], s = signh0[i];
    o_logh[i] = lh;
    o_sign[i] = s;
    g_hbuf[i] = s * expf(lh);
    if (i < 64) g_mbcnt[i] = 0;
    if (i == 0) { g_cnt = 0u; g_arrive = 0u; g_release = 0u; }
}

// ============ combined: 0-127 recurrence, 128+ producer(AD) then consumer(U+compete) ============
__global__ void __launch_bounds__(256) recurrence_kernel(
    const float* __restrict__ Rh, const float* __restrict__ Rd,
    const float* __restrict__ x,  const float* __restrict__ Rx,
    const float* __restrict__ Wdel, const float* __restrict__ Wout,
    const float* __restrict__ bvec, const float* __restrict__ bdel,
    float* __restrict__ o_hlin, float* __restrict__ o_logh, float* __restrict__ o_sign,
    float* __restrict__ out) {

    extern __shared__ float smem[];
    const int tid = threadIdx.x;
    const int bid = blockIdx.x;

    if (bid < REC_CTAS) {
        // ================= RECURRENCE ROLE (R14-verbatim except barrier) =================
        float* W_s  = smem;
        float* h_s  = smem + 16 * 1024;
        float* part = smem + 16 * 1024 + 8 * 1024;
        const int j0  = bid * 8;

        __shared__ float bj_s[8], bdj_s[8];
        __shared__ double ds[64];
        __shared__ int   flag_n;
        __shared__ int   flag_pos[16];
        __shared__ double dred[32];
        if (tid < 8)       bj_s[tid]  = bvec[j0 + tid];
        else if (tid < 16) bdj_s[tid - 8] = bdel[j0 + tid - 8];

        const float s_h = g_scale[0];
        const float s_d = g_scale[1];

        for (int idx = tid; idx < 2048; idx += 256) {
            int row = idx >> 8;
            int c4  = idx & 255;
            float4 a = *(const float4*)(Rh + (size_t)(j0 + row) * DIM + c4 * 4);
            a.x *= s_h; a.y *= s_h; a.z *= s_h; a.w *= s_h;
            ((float4*)(W_s + (size_t)row * DIM))[c4] = a;
            float4 d = *(const float4*)(Rd + (size_t)(j0 + row) * DIM + c4 * 4);
            d.x *= s_d; d.y *= s_d; d.z *= s_d; d.w *= s_d;
            ((float4*)(W_s + (size_t)(8 + row) * DIM))[c4] = d;
        }
        __syncthreads();

        const int w  = tid >> 5, l = tid & 31;
        const int kh = w >> 2;
        const int cg = (w & 3) << 2;
        const int ei  = tid & 63;
        const int elc = ei >> 3, eb = ei & 7;

        for (int t = 0; t < T_STEPS; t++) {
            if ((t & 15) == 0 && t >= PRO_MB * 16) {
                volatile int* c = &g_mbcnt[t >> 4];
                while (*c < 16) { }
            }

            float ad_pf = 0.f;
            {
                size_t prow = (size_t)t * BATCH + eb;
                if (tid < 64)       ad_pf = __ldcg(&g_AD[prow * 2048 + j0 + elc]);
                else if (tid < 128) ad_pf = __ldcg(&g_AD[prow * 2048 + 1024 + j0 + elc]);
            }
            if (tid == 0) flag_n = 0;

            const float* hsrc = g_hbuf + (size_t)(t & 1) * (BATCH * DIM);
            for (int i = tid; i < 2048; i += 256)
                ((float4*)h_s)[i] = __ldcg(((const float4*)hsrc) + i);
            __syncthreads();

            float acc[4][8];
            #pragma unroll
            for (int c = 0; c < 4; c++)
                #pragma unroll
                for (int b = 0; b < 8; b++) acc[c][b] = 0.f;

            #pragma unroll
            for (int i = 0; i < 4; i++) {
                int kb = (kh << 9) + (i << 7) + (l << 2);
                float4 w4[4];
                #pragma unroll
                for (int c = 0; c < 4; c++)
                    w4[c] = *(const float4*)(W_s + (size_t)(cg + c) * DIM + kb);
                #pragma unroll
                for (int b = 0; b < 8; b++) {
                    float4 h4 = *(const float4*)(h_s + (size_t)b * DIM + kb);
                    #pragma unroll
                    for (int c = 0; c < 4; c++)
                        acc[c][b] += w4[c].x * h4.x + w4[c].y * h4.y
                                   + w4[c].z * h4.z + w4[c].w * h4.w;
                }
            }
            #pragma unroll
            for (int o = 16; o; o >>= 1)
                #pragma unroll
                for (int c = 0; c < 4; c++)
                    #pragma unroll
                    for (int b = 0; b < 8; b++)
                        acc[c][b] += __shfl_down_sync(0xffffffffu, acc[c][b], o);
            if (l == 0) {
                #pragma unroll
                for (int c = 0; c < 4; c++)
                    #pragma unroll
                    for (int b = 0; b < 8; b++)
                        part[(cg + c) * 16 + b * 2 + kh] = acc[c][b];
            }
            __syncthreads();

            double cand_r = 0.0;
            if (tid < 64) {
                double hv = (double)part[elc * 16 + eb * 2 + 0] + (double)part[elc * 16 + eb * 2 + 1];
                cand_r = tanh((double)ad_pf + hv + (double)bj_s[elc]);
            } else if (tid < 128) {
                double dv = (double)part[(8 + elc) * 16 + eb * 2 + 0] + (double)part[(8 + elc) * 16 + eb * 2 + 1];
                ds[ei] = 1.0 / (1.0 + exp(-((double)ad_pf + dv + (double)bdj_s[elc])));
            }
            if (tid < 128)
                asm volatile("bar.sync 1, 128;" ::: "memory");

            if (tid < 64) {
                int j = j0 + elc;
                size_t row = (size_t)t * BATCH + eb;
                double delta = ds[ei];
                double hp = (double)h_s[(size_t)eb * DIM + j];
                double hnd = (1.0 - delta) * hp + delta * cand_r;
                float hn = (float)hnd;
                float lh = (float)log((double)fabsf(hn) + 1e-12);
                float sg = (hn >= 0.f) ? 1.f : -1.f;
                __stcg(&g_hbuf[(size_t)((t + 1) & 1) * (BATCH * DIM) + (size_t)eb * DIM + j],
                       sg * (float)exp((double)lh));
                o_hlin[row * DIM + j] = hn;
                o_logh[(row + BATCH) * DIM + j] = lh;
                o_sign[(row + BATCH) * DIM + j] = sg;
                if (fabsf(hn) < 4e-6f) {
                    int fi = atomicAdd(&flag_n, 1);
                    if (fi < 16) flag_pos[fi] = (eb << 16) | elc;
                }
            }
            __syncthreads();

            int nf = flag_n; if (nf > 16) nf = 16;
            for (int f = 0; f < nf; f++) {
                int pb  = flag_pos[f] >> 16;
                int plc = flag_pos[f] & 0xffff;
                int pj  = j0 + plc;
                size_t prow = (size_t)t * BATCH + pb;
                const float* xr = x + prow * DIM;
                const float* hb = h_s + (size_t)pb * DIM;
                double sa = 0, sd2 = 0, sh2 = 0, sv2 = 0;
                for (int k = tid; k < DIM; k += 256) {
                    double xk = (double)xr[k], hk = (double)hb[k];
                    sa  += xk * (double)Rx  [(size_t)pj * DIM + k];
                    sd2 += xk * (double)Wdel[(size_t)pj * DIM + k];
                    sh2 += hk * (double)__fmul_rn(Rh[(size_t)pj * DIM + k], s_h);
                    sv2 += hk * (double)__fmul_rn(Rd[(size_t)pj * DIM + k], s_d);
                }
                #pragma unroll
                for (int o = 16; o; o >>= 1) {
                    sa  += __shfl_down_sync(0xffffffffu, sa,  o);
                    sd2 += __shfl_down_sync(0xffffffffu, sd2, o);
                    sh2 += __shfl_down_sync(0xffffffffu, sh2, o);
                    sv2 += __shfl_down_sync(0xffffffffu, sv2, o);
                }
                if (l == 0) {
                    dred[w] = sa; dred[8 + w] = sd2; dred[16 + w] = sh2; dred[24 + w] = sv2;
                }
                __syncthreads();
                if (tid == 0) {
                    double A0 = 0, D0 = 0, H0 = 0, V0 = 0;
                    #pragma unroll
                    for (int i = 0; i < 8; i++) {
                        A0 += dred[i]; D0 += dred[8 + i]; H0 += dred[16 + i]; V0 += dred[24 + i];
                    }
                    double vv = A0 + H0 + (double)bj_s[plc];
                    double zz = D0 + V0 + (double)bdj_s[plc];
                    double cd = tanh(vv);
                    double dl = 1.0 / (1.0 + exp(-zz));
                    double hpd = (double)hb[pj];
                    double hnd = (1.0 - dl) * hpd + dl * cd;
                    float hnf = (float)hnd;
                    o_hlin[prow * DIM + pj] = hnf;
                    float lh2 = (float)log((double)fabsf(hnf) + 1e-12);
                    float sg2 = (hnf >= 0.f) ? 1.f : -1.f;
                    o_logh[(prow + BATCH) * DIM + pj] = lh2;
                    o_sign[(prow + BATCH) * DIM + pj] = sg2;
                    __stcg(&g_hbuf[(size_t)((t + 1) & 1) * (BATCH * DIM) + (size_t)pb * DIM + pj],
                           sg2 * (float)exp((double)lh2));
                }
                __syncthreads();
            }

            // ---- ONE-LEG barrier: monotone arrival counter, direct poll ----
            {
                unsigned need = (unsigned)(t + 1) * 128u;
                __syncthreads();                       // all stores program-order before arrival
                if (tid == 0) {
                    __threadfence();
                    atomicAdd(&g_cnt, 1u);
                    volatile unsigned* cp = &g_cnt;
                    while (*cp < need) { __nanosleep(30); }
                    __threadfence();
                }
                __syncthreads();
            }
        }
    } else {
        const int cb = bid - REC_CTAS;

        // ========== PHASE A (producer): AD tiles for m-blocks PRO_MB..63 ==========
        const int NTILES_A = (64 - PRO_MB) * 16;
        for (int q = cb; q < NTILES_A; q += CON_CTAS) {
            int mb = PRO_MB + (q >> 4);
            int nt = q & 15;
            ad_tile(x, Rx, Wdel, mb * 128, nt * 128, tid);
            __syncthreads();
            if (tid == 0) {
                __threadfence();
                atomicAdd(&g_mbcnt[mb], 1);
            }
            __syncthreads();
        }

        // ========== PHASE B (consumer): U = hlin @ Wout^T + fused compete ==========
        float* As2 = smem;
        float* Bs2 = smem + 2048;
        float* Ut  = smem + 4096;
        const int lr = tid >> 1;
        const int lk = (tid & 1) * 4;
        const int tx = tid & 15, ty = tid >> 4;
        const int w = tid >> 5, l = tid & 31;

        for (int ti = cb; ti < 512; ti += CON_CTAS) {
            int mb = ti >> 3;
            int nb = ti & 7;
            if (tid == 0) {
                volatile unsigned* cp = &g_cnt;
                unsigned need = (unsigned)((mb + 1) * 16) * 128u;
                while (*cp < need) { __nanosleep(200); }
                __threadfence();
            }
            __syncthreads();

            const int m0 = mb * 128, n0 = nb * 128;
            const float* Aptr = o_hlin + (size_t)(m0 + lr) * DIM + lk;
            const float* Bptr = Wout   + (size_t)(n0 + lr) * DIM + lk;

            float acc[8][8];
            #pragma unroll
            for (int i = 0; i < 8; i++)
                #pragma unroll
                for (int j = 0; j < 8; j++) acc[i][j] = 0.f;

            float4 av = __ldcg((const float4*)Aptr);
            float4 bv = *(const float4*)Bptr;
            As2[(lk + 0) * 128 + lr] = av.x; As2[(lk + 1) * 128 + lr] = av.y;
            As2[(lk + 2) * 128 + lr] = av.z; As2[(lk + 3) * 128 + lr] = av.w;
            Bs2[(lk + 0) * 128 + lr] = bv.x; Bs2[(lk + 1) * 128 + lr] = bv.y;
            Bs2[(lk + 2) * 128 + lr] = bv.z; Bs2[(lk + 3) * 128 + lr] = bv.w;
            __syncthreads();

            int cur = 0;
            for (int k0 = 0; k0 < DIM; k0 += 8) {
                const bool more = (k0 + 8 < DIM);
                if (more) {
                    av = __ldcg((const float4*)(Aptr + k0 + 8));
                    bv = *(const float4*)(Bptr + k0 + 8);
                }
                float* Ac = As2 + cur * 1024;
                float* Bc = Bs2 + cur * 1024;
                #pragma unroll
                for (int kk = 0; kk < 8; kk++) {
                    float a[8], bb[8];
                    *(float4*)(a)      = *(const float4*)&Ac[kk * 128 + ty * 4];
                    *(float4*)(a + 4)  = *(const float4*)&Ac[kk * 128 + 64 + ty * 4];
                    *(float4*)(bb)     = *(const float4*)&Bc[kk * 128 + tx * 4];
                    *(float4*)(bb + 4) = *(const float4*)&Bc[kk * 128 + 64 + tx * 4];
                    #pragma unroll
                    for (int i = 0; i < 8; i++)
                        #pragma unroll
                        for (int j = 0; j < 8; j++)
                            acc[i][j] += a[i] * bb[j];
                }
                if (more) {
                    int nxt = 1 - cur;
                    float* An = As2 + nxt * 1024;
                    float* Bn = Bs2 + nxt * 1024;
                    An[(lk + 0) * 128 + lr] = av.x; An[(lk + 1) * 128 + lr] = av.y;
                    An[(lk + 2) * 128 + lr] = av.z; An[(lk + 3) * 128 + lr] = av.w;
                    Bn[(lk + 0) * 128 + lr] = bv.x; Bn[(lk + 1) * 128 + lr] = bv.y;
                    Bn[(lk + 2) * 128 + lr] = bv.z; Bn[(lk + 3) * 128 + lr] = bv.w;
                    __syncthreads();
                    cur = nxt;
                }
            }

            #pragma unroll
            for (int i = 0; i < 8; i++) {
                int rm = (i < 4) ? (ty * 4 + i) : (64 + ty * 4 + (i - 4));
                *(float4*)&Ut[rm * 128 + tx * 4]      = make_float4(acc[i][0], acc[i][1], acc[i][2], acc[i][3]);
                *(float4*)&Ut[rm * 128 + 64 + tx * 4] = make_float4(acc[i][4], acc[i][5], acc[i][6], acc[i][7]);
            }
            __syncthreads();

            for (int u = w; u < 512; u += 8) {
                int rm = u >> 2;
                int g  = u & 3;
                size_t m = (size_t)m0 + rm;
                int nl = g * 32 + l;
                float h = __ldcg(&o_hlin[m * DIM + n0 + nl]);
                float mx = h;
                #pragma unroll
                for (int o = 16; o; o >>= 1) mx = fmaxf(mx, __shfl_xor_sync(0xffffffffu, mx, o));
                float e = expf(h - mx);
                float sum = e;
                #pragma unroll
                for (int o = 16; o; o >>= 1) sum += __shfl_xor_sync(0xffffffffu, sum, o);
                float uv = Ut[rm * 128 + nl];
                float silu = uv / (1.f + expf(-uv));
                out[m * DIM + n0 + nl] = (e / sum) * silu;
            }
            __syncthreads();
        }
    }
}

extern "C" void kernel_launch(void* const* d_in, const int* in_sizes, int n_in,
                              void* d_out, int out_size) {
    const float* x      = (const float*)d_in[0];
    const float* logh0  = (const float*)d_in[1];
    const float* signh0 = (const float*)d_in[2];
    const float* Rh     = (const float*)d_in[3];
    const float* Rx     = (const float*)d_in[4];
    const float* Rd     = (const float*)d_in[5];
    const float* Wdel   = (const float*)d_in[6];
    const float* Wout   = (const float*)d_in[7];
    const float* bb     = (const float*)d_in[8];
    const float* bdel   = (const float*)d_in[9];
    const float* uh     = (const float*)d_in[10];
    const float* ud     = (const float*)d_in[11];

    float* out    = (float*)d_out;
    float* o_logh = out + (size_t)8388608;
    float* o_sign = out + (size_t)16785408;
    float* o_hlin = out + (size_t)25182208;

    cudaFuncSetAttribute(recurrence_kernel,
                         cudaFuncAttributeMaxDynamicSharedMemorySize, REC_SMEM);
    cudaFuncSetAttribute(sgemm_kernel,
                         cudaFuncAttributeMaxDynamicSharedMemorySize, 4096 * 4);

    init_kernel<<<32, 256>>>(logh0, signh0, o_logh, o_sign);
    spectral_kernel<<<64, 256>>>(Rh, Rd, uh, ud);
    sgemm_kernel<<<dim3(16, PRO_MB), 256, 4096 * 4>>>(x, Rx, Wdel);
    recurrence_kernel<<<REC_CTAS + CON_CTAS, 256, REC_SMEM>>>(
        Rh, Rd, x, Rx, Wdel, Wout, bb, bdel, o_hlin, o_logh, o_sign, out);
}